// round 14
// baseline (speedup 1.0000x reference)
#include <cuda_runtime.h>
#include <float.h>
#include <cstdint>

// ---------------------------------------------------------------------------
// Fused quantizer, bulk-async (TMA) edition.
//   phase 1: cp.async.bulk GMEM->SMEM double-buffered, min/max from SMEM
//   grid barrier (generation ticket, monotonic -> graph-replay safe)
//   phase 2: LDG.128 (L2 hits), quant, STS into SMEM, cp.async.bulk SMEM->GMEM
// Rationale: R8/R13 showed dur pinned at ~62.7us across occupancy 48->72% and
// static vs work-stolen scheduling, with traffic already at the 268MB floor
// and nothing >57% utilized -> per-SM LDG/STG miss-queue (MSHR) service cap.
// Bulk-async engine bypasses that path (LTS-cap ~6300 B/cyc, path-indep).
// ---------------------------------------------------------------------------
#define THREADS 256
#define CHUNK_F4 1024                   // 16 KB chunks
#define MAXB 2048                       // upper bound on grid size

__device__ float g_pmn[MAXB];
__device__ float g_pmx[MAXB];
__device__ unsigned int g_arrive;       // monotonic barrier ticket

__device__ __forceinline__ unsigned smem_u32(const void* p) {
    return (unsigned)__cvta_generic_to_shared(p);
}
__device__ __forceinline__ int imin(int a, int b) { return a < b ? a : b; }

// mbarrier helpers ----------------------------------------------------------
__device__ __forceinline__ void mbar_init(unsigned mb, unsigned count) {
    asm volatile("mbarrier.init.shared.b64 [%0], %1;" :: "r"(mb), "r"(count) : "memory");
}
__device__ __forceinline__ void mbar_expect_tx(unsigned mb, unsigned bytes) {
    asm volatile("mbarrier.arrive.expect_tx.shared.b64 _, [%0], %1;"
                 :: "r"(mb), "r"(bytes) : "memory");
}
__device__ __forceinline__ void mbar_wait(unsigned mb, unsigned parity) {
    asm volatile(
        "{\n\t"
        ".reg .pred P1;\n\t"
        "WAIT_LP_%=:\n\t"
        "mbarrier.try_wait.parity.acquire.cta.shared::cta.b64 P1, [%0], %1, 0x989680;\n\t"
        "@P1 bra.uni WAIT_DN_%=;\n\t"
        "bra.uni WAIT_LP_%=;\n\t"
        "WAIT_DN_%=:\n\t"
        "}"
        :: "r"(mb), "r"(parity) : "memory");
}
// 1D bulk copies -------------------------------------------------------------
__device__ __forceinline__ void bulk_g2s(unsigned smem, const void* gptr,
                                         unsigned bytes, unsigned mb) {
    asm volatile(
        "cp.async.bulk.shared::cluster.global.mbarrier::complete_tx::bytes [%0], [%1], %2, [%3];"
        :: "r"(smem), "l"(gptr), "r"(bytes), "r"(mb) : "memory");
}
__device__ __forceinline__ void bulk_s2g(void* gptr, unsigned smem, unsigned bytes) {
    asm volatile(
        "cp.async.bulk.global.shared::cta.bulk_group [%0], [%1], %2;"
        :: "l"(gptr), "r"(smem), "r"(bytes) : "memory");
}

// quant math (unchanged from the 65.1us passing kernel) -----------------------
__device__ __forceinline__ float quant1(float x, float mn, float step, float inv) {
    float d = x - mn;                 // >= 0 exactly
    float q = d * inv;
    float t = floorf(q);
    float frac = q - t;
    if (frac < 2e-4f || frac > 0.9998f) {
        q = __fdiv_rn(d, step);       // exact IEEE divide, matches reference
        t = floorf(q);
    }
    t = fmaxf(t, 0.0f);
    t = fminf(t, 255.0f);
    return mn + (t + 0.5f) * step;
}
__device__ __forceinline__ float4 quant4(float4 v, float mn, float step, float inv) {
    float4 r;
    r.x = quant1(v.x, mn, step, inv);
    r.y = quant1(v.y, mn, step, inv);
    r.z = quant1(v.z, mn, step, inv);
    r.w = quant1(v.w, mn, step, inv);
    return r;
}

__global__ void __launch_bounds__(THREADS, 6)
fused_quant_kernel(const float4* __restrict__ x4, float4* __restrict__ o4, int n4,
                   const float* __restrict__ x, float* __restrict__ o, int n) {
    __shared__ __align__(128) float4 sbuf[2][CHUNK_F4];   // 32 KB
    __shared__ __align__(8) unsigned long long mbar[2];
    __shared__ float smn[8], smx[8];

    const int tid = threadIdx.x;
    const int G = gridDim.x;
    const int gtid = blockIdx.x * THREADS + tid;
    const int nchunks = (n4 + CHUNK_F4 - 1) / CHUNK_F4;

    // Balanced contiguous split: first `rem` CTAs get base+1 chunks.
    const int cbase = nchunks / G;
    const int crem  = nchunks % G;
    const int c0  = blockIdx.x * cbase + imin(blockIdx.x, crem);
    const int cnt = cbase + (blockIdx.x < crem ? 1 : 0);

    const unsigned mb0 = smem_u32(&mbar[0]);
    const unsigned mb1 = smem_u32(&mbar[1]);
    const unsigned sb0 = smem_u32(&sbuf[0][0]);
    const unsigned sb1 = smem_u32(&sbuf[1][0]);

    if (tid == 0) { mbar_init(mb0, 1); mbar_init(mb1, 1); }
    __syncthreads();

    // ===================== Phase 1: bulk-load + reduce ======================
    float mn =  FLT_MAX;
    float mx = -FLT_MAX;
    unsigned ph0 = 0, ph1 = 0;

    if (cnt > 0 && tid == 0) {
        int gb = c0 * CHUNK_F4;
        unsigned bytes = (unsigned)imin(CHUNK_F4, n4 - gb) * 16u;
        mbar_expect_tx(mb0, bytes);
        bulk_g2s(sb0, (const void*)(x4 + gb), bytes, mb0);
    }
    for (int k = 0; k < cnt; k++) {
        const int p = k & 1;
        if (k + 1 < cnt && tid == 0) {          // prefetch next into other buf
            int gb = (c0 + k + 1) * CHUNK_F4;
            unsigned bytes = (unsigned)imin(CHUNK_F4, n4 - gb) * 16u;
            unsigned mb = p ? mb0 : mb1;
            mbar_expect_tx(mb, bytes);
            bulk_g2s(p ? sb0 : sb1, (const void*)(x4 + gb), bytes, mb);
        }
        if (p == 0) { mbar_wait(mb0, ph0); ph0 ^= 1; }
        else        { mbar_wait(mb1, ph1); ph1 ^= 1; }

        int gb = (c0 + k) * CHUNK_F4;
        int f4c = imin(CHUNK_F4, n4 - gb);
        if (f4c == CHUNK_F4) {
            float4 a = sbuf[p][tid];
            float4 b = sbuf[p][tid + 256];
            float4 c = sbuf[p][tid + 512];
            float4 d = sbuf[p][tid + 768];
            mn = fminf(mn, fminf(fminf(a.x, a.y), fminf(a.z, a.w)));
            mx = fmaxf(mx, fmaxf(fmaxf(a.x, a.y), fmaxf(a.z, a.w)));
            mn = fminf(mn, fminf(fminf(b.x, b.y), fminf(b.z, b.w)));
            mx = fmaxf(mx, fmaxf(fmaxf(b.x, b.y), fmaxf(b.z, b.w)));
            mn = fminf(mn, fminf(fminf(c.x, c.y), fminf(c.z, c.w)));
            mx = fmaxf(mx, fmaxf(fmaxf(c.x, c.y), fmaxf(c.z, c.w)));
            mn = fminf(mn, fminf(fminf(d.x, d.y), fminf(d.z, d.w)));
            mx = fmaxf(mx, fmaxf(fmaxf(d.x, d.y), fmaxf(d.z, d.w)));
        } else {
            #pragma unroll
            for (int j = 0; j < 4; j++) {
                int idx = tid + j * 256;
                if (idx < f4c) {
                    float4 v = sbuf[p][idx];
                    mn = fminf(mn, fminf(fminf(v.x, v.y), fminf(v.z, v.w)));
                    mx = fmaxf(mx, fmaxf(fmaxf(v.x, v.y), fmaxf(v.z, v.w)));
                }
            }
        }
        __syncthreads();                 // all read buf[p] before its reuse
    }
    const int base = n4 << 2;
    if (gtid < (n - base)) {             // scalar tail (n % 4 != 0)
        float v = x[base + gtid];
        mn = fminf(mn, v);
        mx = fmaxf(mx, v);
    }

    // Block reduce -> per-block partial
    #pragma unroll
    for (int s = 16; s > 0; s >>= 1) {
        mn = fminf(mn, __shfl_xor_sync(0xFFFFFFFFu, mn, s));
        mx = fmaxf(mx, __shfl_xor_sync(0xFFFFFFFFu, mx, s));
    }
    const int w = tid >> 5, l = tid & 31;
    if (l == 0) { smn[w] = mn; smx[w] = mx; }
    __syncthreads();
    if (w == 0) {
        mn = (l < 8) ? smn[l] :  FLT_MAX;
        mx = (l < 8) ? smx[l] : -FLT_MAX;
        #pragma unroll
        for (int s = 4; s > 0; s >>= 1) {
            mn = fminf(mn, __shfl_xor_sync(0xFFFFFFFFu, mn, s));
            mx = fmaxf(mx, __shfl_xor_sync(0xFFFFFFFFu, mx, s));
        }
        if (l == 0) { g_pmn[blockIdx.x] = mn; g_pmx[blockIdx.x] = mx; }
    }

    // ===================== Grid barrier (generation ticket) =================
    // Grid is sized host-side from the occupancy API -> all CTAs co-resident.
    if (tid == 0) {
        __threadfence();
        unsigned int ticket = atomicAdd(&g_arrive, 1u);
        unsigned int target = (ticket / (unsigned)G + 1u) * (unsigned)G;
        while (*(volatile unsigned int*)&g_arrive < target) { __nanosleep(32); }
        __threadfence();
    }
    __syncthreads();

    // ===================== Fold partials (every block) ======================
    mn =  FLT_MAX;  mx = -FLT_MAX;
    #pragma unroll 1
    for (int j = tid; j < G; j += THREADS) {
        mn = fminf(mn, g_pmn[j]);
        mx = fmaxf(mx, g_pmx[j]);
    }
    #pragma unroll
    for (int s = 16; s > 0; s >>= 1) {
        mn = fminf(mn, __shfl_xor_sync(0xFFFFFFFFu, mn, s));
        mx = fmaxf(mx, __shfl_xor_sync(0xFFFFFFFFu, mx, s));
    }
    __syncthreads();
    if (l == 0) { smn[w] = mn; smx[w] = mx; }
    __syncthreads();
    mn = smn[0]; mx = smx[0];
    #pragma unroll
    for (int j = 1; j < 8; j++) { mn = fminf(mn, smn[j]); mx = fmaxf(mx, smx[j]); }

    const float step = (mx - mn) * (1.0f / 256.0f);   // /256 exact
    const float inv  = __fdiv_rn(1.0f, step);

    // ===================== Phase 2: quant -> SMEM -> bulk store =============
    if (gtid < (n - base)) {
        o[base + gtid] = quant1(x[base + gtid], mn, step, inv);
    }
    for (int k = cnt - 1; k >= 0; k--) {     // reverse: L2-hot tail first
        const int q = (cnt - 1 - k) & 1;
        if (tid == 0) {                      // buffer q free once <=1 group pending
            asm volatile("cp.async.bulk.wait_group.read 1;" ::: "memory");
        }
        __syncthreads();

        int gb = (c0 + k) * CHUNK_F4;
        int f4c = imin(CHUNK_F4, n4 - gb);
        if (f4c == CHUNK_F4) {
            float4 a = x4[gb + tid];
            float4 b = x4[gb + tid + 256];
            float4 c = x4[gb + tid + 512];
            float4 d = x4[gb + tid + 768];
            sbuf[q][tid]       = quant4(a, mn, step, inv);
            sbuf[q][tid + 256] = quant4(b, mn, step, inv);
            sbuf[q][tid + 512] = quant4(c, mn, step, inv);
            sbuf[q][tid + 768] = quant4(d, mn, step, inv);
        } else {
            #pragma unroll
            for (int j = 0; j < 4; j++) {
                int idx = tid + j * 256;
                if (idx < f4c) {
                    sbuf[q][idx] = quant4(x4[gb + idx], mn, step, inv);
                }
            }
        }
        __syncthreads();                     // all STS complete
        if (tid == 0) {
            asm volatile("fence.proxy.async.shared::cta;" ::: "memory");
            bulk_s2g((void*)(o4 + gb), q ? sb1 : sb0, (unsigned)f4c * 16u);
            asm volatile("cp.async.bulk.commit_group;" ::: "memory");
        }
    }
    if (tid == 0) {                          // drain before kernel exit
        asm volatile("cp.async.bulk.wait_group 0;" ::: "memory");
    }
}

// ---------------------------------------------------------------------------
// Launch: grid sized so all CTAs are co-resident (spin barrier requirement).
// ---------------------------------------------------------------------------
extern "C" void kernel_launch(void* const* d_in, const int* in_sizes, int n_in,
                              void* d_out, int out_size) {
    const float* x = (const float*)d_in[0];
    float* out = (float*)d_out;
    const int n  = in_sizes[0];
    const int n4 = n >> 2;

    int dev = 0;
    cudaGetDevice(&dev);
    int sms = 148;
    cudaDeviceGetAttribute(&sms, cudaDevAttrMultiProcessorCount, dev);
    int occ = 1;
    cudaOccupancyMaxActiveBlocksPerMultiprocessor(&occ, fused_quant_kernel,
                                                  THREADS, 0);
    if (occ < 1) occ = 1;
    int G = sms * occ;
    if (G > MAXB) G = MAXB;
    if (G < 1) G = 1;

    fused_quant_kernel<<<G, THREADS>>>((const float4*)x, (float4*)out, n4,
                                       x, out, n);
}

// round 15
// speedup vs baseline: 1.0550x; 1.0550x over previous
#include <cuda_runtime.h>
#include <float.h>

// ---------------------------------------------------------------------------
// Fused single-kernel quantizer (R15).
//   phase 1: lockstep grid-stride min/max reduce, MLP=8, L2::256B fetch hint
//   grid barrier (generation ticket, monotonic -> graph-replay safe)
//   phase 2: quantize in REVERSE order (L2-hot tail first), __stcs stores
// R15 rationale: four designs pinned at ~63us / 4.7TB/s with DRAM 43% idle ->
// chip-level DRAM row/activate overhead, not SM-side supply. Fetch 256B per
// miss (half the requests, double granularity) + deeper per-warp batching.
// ---------------------------------------------------------------------------
#define CTAS_PER_SM 4
#define NBLOCKS (148 * CTAS_PER_SM)    // 592, co-resident by construction
__device__ float g_pmn[NBLOCKS];
__device__ float g_pmx[NBLOCKS];
__device__ unsigned int g_arrive;      // monotonic barrier ticket

// 128-bit read-only load with 256B L2 fetch granularity (sequential stream ->
// zero waste; halves DRAM request count, improves row locality).
__device__ __forceinline__ float4 ldg256(const float4* p) {
    float4 v;
    asm("ld.global.nc.L2::256B.v4.f32 {%0,%1,%2,%3}, [%4];"
        : "=f"(v.x), "=f"(v.y), "=f"(v.z), "=f"(v.w) : "l"(p));
    return v;
}

__device__ __forceinline__ float quant1(float x, float mn, float step, float inv) {
    float d = x - mn;                 // >= 0 exactly
    float q = d * inv;
    float t = floorf(q);
    float frac = q - t;
    if (frac < 2e-4f || frac > 0.9998f) {
        q = __fdiv_rn(d, step);       // exact IEEE divide, matches reference
        t = floorf(q);
    }
    t = fmaxf(t, 0.0f);
    t = fminf(t, 255.0f);
    return mn + (t + 0.5f) * step;
}

__device__ __forceinline__ float4 quant4(float4 v, float mn, float step, float inv) {
    float4 r;
    r.x = quant1(v.x, mn, step, inv);
    r.y = quant1(v.y, mn, step, inv);
    r.z = quant1(v.z, mn, step, inv);
    r.w = quant1(v.w, mn, step, inv);
    return r;
}

__device__ __forceinline__ void mmfold(float4 v, float& mn, float& mx) {
    mn = fminf(mn, fminf(fminf(v.x, v.y), fminf(v.z, v.w)));
    mx = fmaxf(mx, fmaxf(fmaxf(v.x, v.y), fmaxf(v.z, v.w)));
}

__global__ void __launch_bounds__(256, CTAS_PER_SM)
fused_quant_kernel(const float4* __restrict__ x4, float4* __restrict__ o4, int n4,
                   const float* __restrict__ x, float* __restrict__ o, int n) {
    const int stride = gridDim.x * blockDim.x;
    const int gtid = blockIdx.x * blockDim.x + threadIdx.x;
    const int G = gridDim.x;

    // ===================== Phase 1: min/max reduce (MLP=8) ==================
    float mn =  FLT_MAX;
    float mx = -FLT_MAX;

    int i = gtid;
    for (; i + 7 * stride < n4; i += 8 * stride) {
        float4 v0 = ldg256(&x4[i]);
        float4 v1 = ldg256(&x4[i + stride]);
        float4 v2 = ldg256(&x4[i + 2 * stride]);
        float4 v3 = ldg256(&x4[i + 3 * stride]);
        float4 v4 = ldg256(&x4[i + 4 * stride]);
        float4 v5 = ldg256(&x4[i + 5 * stride]);
        float4 v6 = ldg256(&x4[i + 6 * stride]);
        float4 v7 = ldg256(&x4[i + 7 * stride]);
        mmfold(v0, mn, mx); mmfold(v1, mn, mx);
        mmfold(v2, mn, mx); mmfold(v3, mn, mx);
        mmfold(v4, mn, mx); mmfold(v5, mn, mx);
        mmfold(v6, mn, mx); mmfold(v7, mn, mx);
    }
    #pragma unroll 1
    for (; i < n4; i += stride) {
        mmfold(ldg256(&x4[i]), mn, mx);
    }
    int base = n4 << 2;
    if (gtid < (n - base)) {            // scalar tail (n % 4 != 0)
        float v = x[base + gtid];
        mn = fminf(mn, v);
        mx = fmaxf(mx, v);
    }

    // Block reduce
    #pragma unroll
    for (int o_ = 16; o_ > 0; o_ >>= 1) {
        mn = fminf(mn, __shfl_xor_sync(0xFFFFFFFFu, mn, o_));
        mx = fmaxf(mx, __shfl_xor_sync(0xFFFFFFFFu, mx, o_));
    }
    __shared__ float smn[8], smx[8];
    int w = threadIdx.x >> 5;
    int l = threadIdx.x & 31;
    if (l == 0) { smn[w] = mn; smx[w] = mx; }
    __syncthreads();
    if (w == 0) {
        mn = (l < 8) ? smn[l] :  FLT_MAX;
        mx = (l < 8) ? smx[l] : -FLT_MAX;
        #pragma unroll
        for (int o_ = 4; o_ > 0; o_ >>= 1) {
            mn = fminf(mn, __shfl_xor_sync(0xFFFFFFFFu, mn, o_));
            mx = fmaxf(mx, __shfl_xor_sync(0xFFFFFFFFu, mx, o_));
        }
        if (l == 0) {
            g_pmn[blockIdx.x] = mn;
            g_pmx[blockIdx.x] = mx;
        }
    }

    // ===================== Grid barrier (generation ticket) =================
    // All NBLOCKS CTAs co-resident (launch bounds) -> spin cannot deadlock.
    // Monotonic counter: replay k waits for k*G arrivals -> replay-safe.
    if (threadIdx.x == 0) {
        __threadfence();                               // publish partials
        unsigned int ticket = atomicAdd(&g_arrive, 1u);
        unsigned int target = (ticket / G + 1u) * G;
        while (*(volatile unsigned int*)&g_arrive < target) {
            __nanosleep(32);
        }
        __threadfence();                               // acquire partials
    }
    __syncthreads();

    // ===================== Fold partials (every block) ======================
    mn =  FLT_MAX;
    mx = -FLT_MAX;
    #pragma unroll 1
    for (int j = threadIdx.x; j < G; j += 256) {
        mn = fminf(mn, g_pmn[j]);
        mx = fmaxf(mx, g_pmx[j]);
    }
    #pragma unroll
    for (int o_ = 16; o_ > 0; o_ >>= 1) {
        mn = fminf(mn, __shfl_xor_sync(0xFFFFFFFFu, mn, o_));
        mx = fmaxf(mx, __shfl_xor_sync(0xFFFFFFFFu, mx, o_));
    }
    __syncthreads();                    // smn/smx reuse
    if (l == 0) { smn[w] = mn; smx[w] = mx; }
    __syncthreads();
    mn = smn[0]; mx = smx[0];
    #pragma unroll
    for (int j = 1; j < 8; j++) {
        mn = fminf(mn, smn[j]);
        mx = fmaxf(mx, smx[j]);
    }

    // step = (max - min)/256 exactly (power-of-2 scale)
    float step = (mx - mn) * (1.0f / 256.0f);
    float inv  = __fdiv_rn(1.0f, step);

    // ===================== Phase 2: quantize (reverse order) ================
    // Walk indices from high to low so the tail of phase 1 (still L2-hot)
    // is consumed before the output stream can evict it.
    if (gtid < (n - base)) {
        o[base + gtid] = quant1(x[base + gtid], mn, step, inv);
    }
    if (gtid < n4) {
        int k = (n4 - 1 - gtid) / stride;      // highest iteration index
        for (; k >= 3; k -= 4) {
            int i0 = gtid + (k - 3) * stride;
            float4 a = x4[i0];
            float4 b = x4[i0 + stride];
            float4 c = x4[i0 + 2 * stride];
            float4 d = x4[i0 + 3 * stride];
            __stcs(&o4[i0],              quant4(a, mn, step, inv));
            __stcs(&o4[i0 + stride],     quant4(b, mn, step, inv));
            __stcs(&o4[i0 + 2 * stride], quant4(c, mn, step, inv));
            __stcs(&o4[i0 + 3 * stride], quant4(d, mn, step, inv));
        }
        #pragma unroll 1
        for (; k >= 0; k--) {
            int i0 = gtid + k * stride;
            __stcs(&o4[i0], quant4(x4[i0], mn, step, inv));
        }
    }
}

// ---------------------------------------------------------------------------
// Launch
// ---------------------------------------------------------------------------
extern "C" void kernel_launch(void* const* d_in, const int* in_sizes, int n_in,
                              void* d_out, int out_size) {
    const float* x = (const float*)d_in[0];
    float* out = (float*)d_out;
    const int n  = in_sizes[0];
    const int n4 = n >> 2;

    fused_quant_kernel<<<NBLOCKS, 256>>>((const float4*)x, (float4*)out, n4,
                                         x, out, n);
}